// round 1
// baseline (speedup 1.0000x reference)
#include <cuda_runtime.h>

#define NN 20000
#define EE 160000
#define GG 64
#define MAXD 512

// Scratch (device globals — no allocation allowed)
__device__ float g_bufA[NN * MAXD];
__device__ float g_bufB[NN * MAXD];
__device__ float g_agg[NN * MAXD];
__device__ int   g_deg[NN];
__device__ int   g_rowptr[NN + 1];
__device__ int   g_fill[NN];
__device__ int   g_csr[EE];
__device__ float g_pool[GG * 256];
__device__ int   g_gs[GG];
__device__ int   g_ge[GG];

__global__ void k_init() {
    int i = blockIdx.x * blockDim.x + threadIdx.x;
    if (i < NN) g_deg[i] = 0;
    if (i < GG) { g_gs[i] = NN; g_ge[i] = 0; }
}

__global__ void k_count(const int* __restrict__ ei) {
    int e = blockIdx.x * blockDim.x + threadIdx.x;
    if (e < EE) atomicAdd(&g_deg[ei[EE + e]], 1);
}

// Single-block exclusive scan over g_deg -> g_rowptr / g_fill
__global__ void k_scan() {
    __shared__ int part[1024];
    int tid = threadIdx.x;
    const int CH = (NN + 1023) / 1024;  // 20
    int base = tid * CH;
    int s = 0;
    for (int i = 0; i < CH; i++) { int idx = base + i; if (idx < NN) s += g_deg[idx]; }
    part[tid] = s;
    __syncthreads();
    for (int off = 1; off < 1024; off <<= 1) {
        int v = (tid >= off) ? part[tid - off] : 0;
        __syncthreads();
        part[tid] += v;
        __syncthreads();
    }
    int run = (tid == 0) ? 0 : part[tid - 1];
    for (int i = 0; i < CH; i++) {
        int idx = base + i;
        if (idx < NN) {
            int c = g_deg[idx];
            g_rowptr[idx] = run;
            g_fill[idx] = run;
            run += c;
        }
    }
    if (tid == 1023) g_rowptr[NN] = part[1023];
}

__global__ void k_fillcsr(const int* __restrict__ ei) {
    int e = blockIdx.x * blockDim.x + threadIdx.x;
    if (e < EE) {
        int d = ei[EE + e];
        int p = atomicAdd(&g_fill[d], 1);
        g_csr[p] = ei[e];
    }
}

// Mean-aggregate neighbor rows: one warp per node, float4 lanes.
__global__ void k_agg(const float* __restrict__ H, int K) {
    int node = blockIdx.x * 8 + (threadIdx.x >> 5);
    if (node >= NN) return;
    int lane = threadIdx.x & 31;
    int beg = g_rowptr[node], end = g_rowptr[node + 1];
    int K4 = K >> 2;
    int np = K4 >> 5;  // 1 (K=128), 2 (256), 4 (512)
    float4 acc[4];
#pragma unroll
    for (int p = 0; p < 4; p++) acc[p] = make_float4(0.f, 0.f, 0.f, 0.f);
    for (int e = beg; e < end; e++) {
        const float4* row = (const float4*)(H + (size_t)g_csr[e] * K);
        for (int p = 0; p < np; p++) {
            float4 v = row[lane + (p << 5)];
            acc[p].x += v.x; acc[p].y += v.y; acc[p].z += v.z; acc[p].w += v.w;
        }
    }
    int d = end - beg;
    float inv = 1.0f / (float)(d > 0 ? d : 1);
    float4* out = (float4*)(g_agg + (size_t)node * K);
    for (int p = 0; p < np; p++) {
        float4 v = acc[p];
        v.x *= inv; v.y *= inv; v.z *= inv; v.w *= inv;
        out[lane + (p << 5)] = v;
    }
}

// Fused dual GEMM: O = A1@Wl + A2@Wr + bl, optional LeakyReLU(0.01).
// 64x64 tile, BK=16, 256 threads, 4x4 per thread.
template <bool LEAKY>
__global__ void k_gemm(const float* __restrict__ A1, const float* __restrict__ A2,
                       const float* __restrict__ Wl, const float* __restrict__ Wr,
                       const float* __restrict__ bl, float* __restrict__ O,
                       int K, int DOUT) {
    __shared__ float sA1[16][64], sA2[16][64], sB1[16][64], sB2[16][64];
    int t = threadIdx.x;
    int tx = t & 15, ty = t >> 4;
    int m0 = blockIdx.y * 64;
    int n0 = blockIdx.x * 64;
    float acc[4][4];
#pragma unroll
    for (int i = 0; i < 4; i++)
#pragma unroll
        for (int j = 0; j < 4; j++) acc[i][j] = 0.f;

    int arow = t >> 2, aq = (t & 3) * 4;   // A tile: 64 rows x 16 cols, float4 along K
    int brow = t >> 4, bc = (t & 15) * 4;  // B tile: 16 rows x 64 cols, float4 along N

    for (int k0 = 0; k0 < K; k0 += 16) {
        float4 v1 = make_float4(0.f, 0.f, 0.f, 0.f), v2 = v1;
        int gr = m0 + arow;
        if (gr < NN) {
            v1 = *(const float4*)&A1[(size_t)gr * K + k0 + aq];
            v2 = *(const float4*)&A2[(size_t)gr * K + k0 + aq];
        }
        sA1[aq + 0][arow] = v1.x; sA1[aq + 1][arow] = v1.y;
        sA1[aq + 2][arow] = v1.z; sA1[aq + 3][arow] = v1.w;
        sA2[aq + 0][arow] = v2.x; sA2[aq + 1][arow] = v2.y;
        sA2[aq + 2][arow] = v2.z; sA2[aq + 3][arow] = v2.w;
        *(float4*)&sB1[brow][bc] = *(const float4*)&Wl[(size_t)(k0 + brow) * DOUT + n0 + bc];
        *(float4*)&sB2[brow][bc] = *(const float4*)&Wr[(size_t)(k0 + brow) * DOUT + n0 + bc];
        __syncthreads();
#pragma unroll
        for (int kk = 0; kk < 16; kk++) {
            float4 a1 = *(float4*)&sA1[kk][ty * 4];
            float4 a2 = *(float4*)&sA2[kk][ty * 4];
            float4 b1 = *(float4*)&sB1[kk][tx * 4];
            float4 b2 = *(float4*)&sB2[kk][tx * 4];
            float a1v[4] = {a1.x, a1.y, a1.z, a1.w};
            float a2v[4] = {a2.x, a2.y, a2.z, a2.w};
            float b1v[4] = {b1.x, b1.y, b1.z, b1.w};
            float b2v[4] = {b2.x, b2.y, b2.z, b2.w};
#pragma unroll
            for (int i = 0; i < 4; i++)
#pragma unroll
                for (int j = 0; j < 4; j++)
                    acc[i][j] += a1v[i] * b1v[j] + a2v[i] * b2v[j];
        }
        __syncthreads();
    }
#pragma unroll
    for (int i = 0; i < 4; i++) {
        int gr = m0 + ty * 4 + i;
        if (gr >= NN) continue;
#pragma unroll
        for (int j = 0; j < 4; j++) {
            int gc = n0 + tx * 4 + j;
            float v = acc[i][j] + bl[gc];
            if (LEAKY) v = (v >= 0.f) ? v : 0.01f * v;
            O[(size_t)gr * DOUT + gc] = v;
        }
    }
}

__global__ void k_bounds(const int* __restrict__ batch) {
    int n = blockIdx.x * blockDim.x + threadIdx.x;
    if (n < NN) {
        int b = batch[n];
        atomicMin(&g_gs[b], n);
        atomicMax(&g_ge[b], n + 1);
    }
}

// batch is sorted -> each graph's nodes are contiguous [gs, ge)
__global__ void k_pool(const float* __restrict__ H) {
    int g = blockIdx.x, f = threadIdx.x;
    int s = g_gs[g], e = g_ge[g];
    float sum = 0.f;
    for (int n = s; n < e; n++) sum += H[(size_t)n * 256 + f];
    int c = e - s;
    if (c < 1) c = 1;
    g_pool[g * 256 + f] = sum / (float)c;
}

__global__ void k_final(const float* __restrict__ Wlin, const float* __restrict__ blin,
                        float* __restrict__ out) {
    int idx = threadIdx.x;
    if (idx >= GG * 6) return;
    int g = idx / 6, o = idx % 6;
    float s = blin[o];
#pragma unroll 8
    for (int k = 0; k < 256; k++) s += g_pool[g * 256 + k] * Wlin[k * 6 + o];
    out[idx] = s;
}

extern "C" void kernel_launch(void* const* d_in, const int* in_sizes, int n_in,
                              void* d_out, int out_size) {
    const float* x     = (const float*)d_in[0];
    const int*   ei    = (const int*)d_in[1];
    const int*   batch = (const int*)d_in[2];
    const float* Wl[6]; const float* blp[6]; const float* Wr[6];
    for (int l = 0; l < 6; l++) {
        Wl[l]  = (const float*)d_in[3 + 3 * l];
        blp[l] = (const float*)d_in[4 + 3 * l];
        Wr[l]  = (const float*)d_in[5 + 3 * l];
    }
    const float* Wlin = (const float*)d_in[21];
    const float* blin = (const float*)d_in[22];
    float* out = (float*)d_out;

    float *bufA, *bufB, *agg;
    cudaGetSymbolAddress((void**)&bufA, g_bufA);
    cudaGetSymbolAddress((void**)&bufB, g_bufB);
    cudaGetSymbolAddress((void**)&agg, g_agg);

    // Build CSR (by dst) each launch — deterministic structure, cheap.
    k_init<<<(NN + 255) / 256, 256>>>();
    k_count<<<(EE + 255) / 256, 256>>>(ei);
    k_scan<<<1, 1024>>>();
    k_fillcsr<<<(EE + 255) / 256, 256>>>(ei);

    const int din[6]  = {128, 256, 256, 512, 512, 256};
    const int dout[6] = {256, 256, 512, 512, 256, 256};
    const float* h = x;
    float* nxt = bufA;
    for (int l = 0; l < 6; l++) {
        k_agg<<<(NN + 7) / 8, 256>>>(h, din[l]);
        dim3 grid(dout[l] / 64, (NN + 63) / 64);
        if (l < 5)
            k_gemm<true><<<grid, 256>>>(agg, h, Wl[l], Wr[l], blp[l], nxt, din[l], dout[l]);
        else
            k_gemm<false><<<grid, 256>>>(agg, h, Wl[l], Wr[l], blp[l], nxt, din[l], dout[l]);
        h = nxt;
        nxt = (nxt == bufA) ? bufB : bufA;
    }
    k_bounds<<<(NN + 255) / 256, 256>>>(batch);
    k_pool<<<GG, 256>>>(h);
    k_final<<<1, 384>>>(Wlin, blin, out);
}

// round 3
// speedup vs baseline: 1.5741x; 1.5741x over previous
#include <cuda_runtime.h>
#include <cuda_bf16.h>
#include <cstdint>

#define NN 20000
#define EE 160000
#define GG 64
#define MAXD 512
#define WTOT 688128

// ---------------- scratch (device globals; no allocation allowed) ----------
__device__ float g_bufA[NN * MAXD];
__device__ float g_bufB[NN * MAXD];
__device__ float g_agg[NN * MAXD];
__device__ float g_WlT[WTOT];
__device__ float g_WrT[WTOT];
__device__ int   g_deg[NN];
__device__ int   g_rowptr[NN + 1];
__device__ int   g_fill[NN];
__device__ int   g_csr[EE];
__device__ float g_pool[GG * 256];
__device__ int   g_gs[GG];
__device__ int   g_ge[GG];

// ---------------- helpers ----------------------------------------------------
__device__ __forceinline__ uint32_t smem_u32(const void* p) {
    uint32_t a;
    asm("{ .reg .u64 t; cvta.to.shared.u64 t, %1; cvt.u32.u64 %0, t; }" : "=r"(a) : "l"(p));
    return a;
}
// pack two f32 -> bf16x2 (low16 = a, high16 = b)
__device__ __forceinline__ uint32_t pk2(float a, float b) {
    uint32_t r;
    asm("cvt.rn.bf16x2.f32 %0, %1, %2;" : "=r"(r) : "f"(b), "f"(a));
    return r;
}
__device__ __forceinline__ void ldm4(uint32_t* r, uint32_t a) {
    asm volatile("ldmatrix.sync.aligned.m8n8.x4.shared.b16 {%0,%1,%2,%3}, [%4];"
                 : "=r"(r[0]), "=r"(r[1]), "=r"(r[2]), "=r"(r[3]) : "r"(a));
}
__device__ __forceinline__ void ldm2(uint32_t* r, uint32_t a) {
    asm volatile("ldmatrix.sync.aligned.m8n8.x2.shared.b16 {%0,%1}, [%2];"
                 : "=r"(r[0]), "=r"(r[1]) : "r"(a));
}
#define MMA_BF16(c, a, b)                                                          \
    asm volatile("mma.sync.aligned.m16n8k16.row.col.f32.bf16.bf16.f32 "            \
        "{%0,%1,%2,%3}, {%4,%5,%6,%7}, {%8,%9}, {%0,%1,%2,%3};"                     \
        : "+f"((c)[0]), "+f"((c)[1]), "+f"((c)[2]), "+f"((c)[3])                    \
        : "r"((a)[0]), "r"((a)[1]), "r"((a)[2]), "r"((a)[3]),                       \
          "r"((b)[0]), "r"((b)[1]))

// ---------------- CSR build -------------------------------------------------
__global__ void k_init() {
    int i = blockIdx.x * blockDim.x + threadIdx.x;
    if (i < NN) g_deg[i] = 0;
    if (i < GG) { g_gs[i] = NN; g_ge[i] = 0; }
}
__global__ void k_count(const int* __restrict__ ei) {
    int e = blockIdx.x * blockDim.x + threadIdx.x;
    if (e < EE) atomicAdd(&g_deg[ei[EE + e]], 1);
}
__global__ void k_scan() {
    __shared__ int part[1024];
    int tid = threadIdx.x;
    const int CH = (NN + 1023) / 1024;
    int base = tid * CH, s = 0;
    for (int i = 0; i < CH; i++) { int idx = base + i; if (idx < NN) s += g_deg[idx]; }
    part[tid] = s;
    __syncthreads();
    for (int off = 1; off < 1024; off <<= 1) {
        int v = (tid >= off) ? part[tid - off] : 0;
        __syncthreads(); part[tid] += v; __syncthreads();
    }
    int run = (tid == 0) ? 0 : part[tid - 1];
    for (int i = 0; i < CH; i++) {
        int idx = base + i;
        if (idx < NN) { int c = g_deg[idx]; g_rowptr[idx] = run; g_fill[idx] = run; run += c; }
    }
    if (tid == 1023) g_rowptr[NN] = part[1023];
}
__global__ void k_fillcsr(const int* __restrict__ ei) {
    int e = blockIdx.x * blockDim.x + threadIdx.x;
    if (e < EE) { int d = ei[EE + e]; int p = atomicAdd(&g_fill[d], 1); g_csr[p] = ei[e]; }
}

// ---------------- mean aggregation (warp/node) ------------------------------
__global__ void k_agg(const float* __restrict__ H, int K) {
    int node = blockIdx.x * 8 + (threadIdx.x >> 5);
    if (node >= NN) return;
    int lane = threadIdx.x & 31;
    int beg = g_rowptr[node], end = g_rowptr[node + 1];
    int np = (K >> 2) >> 5;
    float4 acc[4];
#pragma unroll
    for (int p = 0; p < 4; p++) acc[p] = make_float4(0.f, 0.f, 0.f, 0.f);
    for (int e = beg; e < end; e++) {
        const float4* row = (const float4*)(H + (size_t)g_csr[e] * K);
        for (int p = 0; p < np; p++) {
            float4 v = row[lane + (p << 5)];
            acc[p].x += v.x; acc[p].y += v.y; acc[p].z += v.z; acc[p].w += v.w;
        }
    }
    int d = end - beg;
    float inv = 1.0f / (float)(d > 0 ? d : 1);
    float4* out = (float4*)(g_agg + (size_t)node * K);
    for (int p = 0; p < np; p++) {
        float4 v = acc[p];
        v.x *= inv; v.y *= inv; v.z *= inv; v.w *= inv;
        out[lane + (p << 5)] = v;
    }
}

// ---------------- weight transpose: WT[n*K+k] = W[k*N+n] --------------------
__global__ void k_tr(const float* __restrict__ W, float* __restrict__ WT, int K, int Ncol) {
    int i = blockIdx.x * 256 + threadIdx.x;
    if (i < K * Ncol) { int k = i / Ncol, n = i % Ncol; WT[(size_t)n * K + k] = W[i]; }
}

// ---------------- bf16 3x-split dual GEMM (mma.sync, tensor pipe) -----------
// D[128,128-tile] = A1@W1T^T + A2@W2T^T (+bias, opt LeakyReLU)
// smem rows: 128 bytes = [hi bf16[32] | lo bf16[32]], SW128 swizzled.
template <bool LEAKY>
__global__ void __launch_bounds__(256) k_gemm_tc(
    const float* __restrict__ A1, const float* __restrict__ A2,
    const float* __restrict__ W1, const float* __restrict__ W2,
    const float* __restrict__ bias, float* __restrict__ O,
    int K, int DOUT)
{
    __shared__ __align__(16) char sA[16384];
    __shared__ __align__(16) char sB[16384];
    const int t = threadIdx.x, lane = t & 31, wid = t >> 5;
    const int wr = wid >> 2, wc = wid & 3;
    const int m0 = blockIdx.y * 128, n0 = blockIdx.x * 128;

    float acc[4][4][4];
#pragma unroll
    for (int i = 0; i < 4; i++)
#pragma unroll
        for (int j = 0; j < 4; j++)
#pragma unroll
            for (int k = 0; k < 4; k++) acc[i][j][k] = 0.f;

    const int nc = K / 32, tot = 2 * nc;
    const int lrow = t & 127;
    const int lq0 = (t >> 7) * 4;  // q = lq0 + i, i in 0..3
    const uint32_t sAb = smem_u32(sA), sBb = smem_u32(sB);

    // STS bases (per-thread, row fixed)
    const uint32_t stxor = (uint32_t)(lrow & 7) << 4;

    // ldmatrix address components (row low-3 bits == lane&7 for both A and B)
    const int arow = wr * 64 + (lane & 7) + ((lane >> 3) & 1) * 8;
    const uint32_t achk = ((uint32_t)(lane >> 4)) * 16;
    const int brow = wc * 32 + (lane & 7);
    const uint32_t bchk = ((uint32_t)((lane >> 3) & 1)) * 16;
    const uint32_t lxor = (uint32_t)(lane & 7) << 4;

    float4 ra[4], rb[4];

    // fetch chunk 0
    {
        const float* sa = A1; const float* sw = W1; int kb = 0;
        int gr = m0 + lrow;
#pragma unroll
        for (int i = 0; i < 4; i++) {
            int q = lq0 + i;
            ra[i] = (gr < NN) ? *(const float4*)(sa + (size_t)gr * K + kb + q * 4)
                              : make_float4(0.f, 0.f, 0.f, 0.f);
            rb[i] = *(const float4*)(sw + (size_t)(n0 + lrow) * K + kb + q * 4);
        }
    }

    for (int ch = 0; ch < tot; ch++) {
        __syncthreads();  // previous chunk consumed
        // convert + store current chunk
#pragma unroll
        for (int i = 0; i < 4; i++) {
            int q = lq0 + i;
            uint32_t offh = ((uint32_t)(q * 8)) ^ stxor;
            uint32_t offl = ((uint32_t)(64 + q * 8)) ^ stxor;
            {
                float4 v = ra[i];
                uint32_t h0 = pk2(v.x, v.y), h1 = pk2(v.z, v.w);
                float fx = __uint_as_float(h0 << 16);
                float fy = __uint_as_float(h0 & 0xFFFF0000u);
                float fz = __uint_as_float(h1 << 16);
                float fw = __uint_as_float(h1 & 0xFFFF0000u);
                uint32_t l0 = pk2(v.x - fx, v.y - fy), l1 = pk2(v.z - fz, v.w - fw);
                *(uint2*)(sA + lrow * 128 + offh) = make_uint2(h0, h1);
                *(uint2*)(sA + lrow * 128 + offl) = make_uint2(l0, l1);
            }
            {
                float4 v = rb[i];
                uint32_t h0 = pk2(v.x, v.y), h1 = pk2(v.z, v.w);
                float fx = __uint_as_float(h0 << 16);
                float fy = __uint_as_float(h0 & 0xFFFF0000u);
                float fz = __uint_as_float(h1 << 16);
                float fw = __uint_as_float(h1 & 0xFFFF0000u);
                uint32_t l0 = pk2(v.x - fx, v.y - fy), l1 = pk2(v.z - fz, v.w - fw);
                *(uint2*)(sB + lrow * 128 + offh) = make_uint2(h0, h1);
                *(uint2*)(sB + lrow * 128 + offl) = make_uint2(l0, l1);
            }
        }
        __syncthreads();

        // prefetch next chunk into registers (hidden behind MMA below)
        if (ch + 1 < tot) {
            int nch = ch + 1;
            const float* sa; const float* sw; int kb;
            if (nch < nc) { sa = A1; sw = W1; kb = nch * 32; }
            else          { sa = A2; sw = W2; kb = (nch - nc) * 32; }
            int gr = m0 + lrow;
#pragma unroll
            for (int i = 0; i < 4; i++) {
                int q = lq0 + i;
                ra[i] = (gr < NN) ? *(const float4*)(sa + (size_t)gr * K + kb + q * 4)
                                  : make_float4(0.f, 0.f, 0.f, 0.f);
                rb[i] = *(const float4*)(sw + (size_t)(n0 + lrow) * K + kb + q * 4);
            }
        }

        // MMA over current chunk (two k16 steps)
#pragma unroll
        for (int ks = 0; ks < 2; ks++) {
            uint32_t ah[4][4], al[4][4], bh[4][2], bl[4][2];
#pragma unroll
            for (int mt = 0; mt < 4; mt++) {
                uint32_t base = sAb + (uint32_t)(arow + mt * 16) * 128;
                ldm4(ah[mt], base + (((uint32_t)(ks * 32) + achk) ^ lxor));
                ldm4(al[mt], base + (((uint32_t)(64 + ks * 32) + achk) ^ lxor));
            }
#pragma unroll
            for (int nt = 0; nt < 4; nt++) {
                uint32_t base = sBb + (uint32_t)(brow + nt * 8) * 128;
                ldm2(bh[nt], base + (((uint32_t)(ks * 32) + bchk) ^ lxor));
                ldm2(bl[nt], base + (((uint32_t)(64 + ks * 32) + bchk) ^ lxor));
            }
#pragma unroll
            for (int mt = 0; mt < 4; mt++)
#pragma unroll
                for (int nt = 0; nt < 4; nt++) {
                    MMA_BF16(acc[mt][nt], ah[mt], bh[nt]);
                    MMA_BF16(acc[mt][nt], ah[mt], bl[nt]);
                    MMA_BF16(acc[mt][nt], al[mt], bh[nt]);
                }
        }
    }

    // epilogue: bias + optional leaky, f32 out
#pragma unroll
    for (int mt = 0; mt < 4; mt++) {
        int r0 = m0 + wr * 64 + mt * 16 + (lane >> 2);
        int r1 = r0 + 8;
#pragma unroll
        for (int nt = 0; nt < 4; nt++) {
            int c0 = n0 + wc * 32 + nt * 8 + (lane & 3) * 2;
            float2 b2 = *(const float2*)(bias + c0);
            float v0 = acc[mt][nt][0] + b2.x;
            float v1 = acc[mt][nt][1] + b2.y;
            float v2 = acc[mt][nt][2] + b2.x;
            float v3 = acc[mt][nt][3] + b2.y;
            if (LEAKY) {
                v0 = v0 >= 0.f ? v0 : 0.01f * v0;
                v1 = v1 >= 0.f ? v1 : 0.01f * v1;
                v2 = v2 >= 0.f ? v2 : 0.01f * v2;
                v3 = v3 >= 0.f ? v3 : 0.01f * v3;
            }
            if (r0 < NN) *(float2*)(O + (size_t)r0 * DOUT + c0) = make_float2(v0, v1);
            if (r1 < NN) *(float2*)(O + (size_t)r1 * DOUT + c0) = make_float2(v2, v3);
        }
    }
}

// ---------------- pool + head ------------------------------------------------
__global__ void k_bounds(const int* __restrict__ batch) {
    int n = blockIdx.x * blockDim.x + threadIdx.x;
    if (n < NN) {
        int b = batch[n];
        atomicMin(&g_gs[b], n);
        atomicMax(&g_ge[b], n + 1);
    }
}
__global__ void k_pool(const float* __restrict__ H) {
    int g = blockIdx.x, f = threadIdx.x;
    int s = g_gs[g], e = g_ge[g];
    float sum = 0.f;
    for (int n = s; n < e; n++) sum += H[(size_t)n * 256 + f];
    int c = e - s; if (c < 1) c = 1;
    g_pool[g * 256 + f] = sum / (float)c;
}
__global__ void k_final(const float* __restrict__ Wlin, const float* __restrict__ blin,
                        float* __restrict__ out) {
    int idx = threadIdx.x;
    if (idx >= GG * 6) return;
    int g = idx / 6, o = idx % 6;
    float s = blin[o];
#pragma unroll 8
    for (int k = 0; k < 256; k++) s += g_pool[g * 256 + k] * Wlin[k * 6 + o];
    out[idx] = s;
}

// ---------------- launcher ----------------------------------------------------
extern "C" void kernel_launch(void* const* d_in, const int* in_sizes, int n_in,
                              void* d_out, int out_size) {
    const float* x     = (const float*)d_in[0];
    const int*   ei    = (const int*)d_in[1];
    const int*   batch = (const int*)d_in[2];
    const float* Wl[6]; const float* blp[6]; const float* Wr[6];
    for (int l = 0; l < 6; l++) {
        Wl[l]  = (const float*)d_in[3 + 3 * l];
        blp[l] = (const float*)d_in[4 + 3 * l];
        Wr[l]  = (const float*)d_in[5 + 3 * l];
    }
    const float* Wlin = (const float*)d_in[21];
    const float* blin = (const float*)d_in[22];
    float* out = (float*)d_out;

    float *bufA, *bufB, *agg, *wlT, *wrT;
    cudaGetSymbolAddress((void**)&bufA, g_bufA);
    cudaGetSymbolAddress((void**)&bufB, g_bufB);
    cudaGetSymbolAddress((void**)&agg, g_agg);
    cudaGetSymbolAddress((void**)&wlT, g_WlT);
    cudaGetSymbolAddress((void**)&wrT, g_WrT);

    const int din[6]  = {128, 256, 256, 512, 512, 256};
    const int dout[6] = {256, 256, 512, 512, 256, 256};
    const int woff[6] = {0, 32768, 98304, 229376, 491520, 622592};

    // CSR build
    k_init<<<(NN + 255) / 256, 256>>>();
    k_count<<<(EE + 255) / 256, 256>>>(ei);
    k_scan<<<1, 1024>>>();
    k_fillcsr<<<(EE + 255) / 256, 256>>>(ei);

    // Weight transposes to K-major [dout, din]
    for (int l = 0; l < 6; l++) {
        int sz = din[l] * dout[l];
        k_tr<<<(sz + 255) / 256, 256>>>(Wl[l], wlT + woff[l], din[l], dout[l]);
        k_tr<<<(sz + 255) / 256, 256>>>(Wr[l], wrT + woff[l], din[l], dout[l]);
    }

    const float* h = x;
    float* nxt = bufA;
    for (int l = 0; l < 6; l++) {
        k_agg<<<(NN + 7) / 8, 256>>>(h, din[l]);
        dim3 grid(dout[l] / 128, (NN + 127) / 128);
        if (l < 5)
            k_gemm_tc<true><<<grid, 256>>>(agg, h, wlT + woff[l], wrT + woff[l],
                                           blp[l], nxt, din[l], dout[l]);
        else
            k_gemm_tc<false><<<grid, 256>>>(agg, h, wlT + woff[l], wrT + woff[l],
                                            blp[l], nxt, din[l], dout[l]);
        h = nxt;
        nxt = (nxt == bufA) ? bufB : bufA;
    }
    k_bounds<<<(NN + 255) / 256, 256>>>(batch);
    k_pool<<<GG, 256>>>(h);
    k_final<<<1, 384>>>(Wlin, blin, out);
}

// round 4
// speedup vs baseline: 2.2023x; 1.3991x over previous
#include <cuda_runtime.h>
#include <cuda_bf16.h>
#include <cstdint>

#define NN 20000
#define EE 160000
#define GG 64
#define MAXD 512
#define WTOT 688128

// ---------------- scratch (device globals; no allocation allowed) ----------
// bf16 planes stored as ushort arrays (bit-identical), 16B aligned.
__device__ __align__(16) unsigned short g_xh[NN * 128];
__device__ __align__(16) unsigned short g_xl[NN * 128];
__device__ __align__(16) unsigned short g_agh[NN * MAXD];
__device__ __align__(16) unsigned short g_agl[NN * MAXD];
__device__ __align__(16) unsigned short g_Ah[NN * MAXD];
__device__ __align__(16) unsigned short g_Al[NN * MAXD];
__device__ __align__(16) unsigned short g_Bh[NN * MAXD];
__device__ __align__(16) unsigned short g_Bl[NN * MAXD];
__device__ __align__(16) unsigned short g_wlh[WTOT];
__device__ __align__(16) unsigned short g_wll[WTOT];
__device__ __align__(16) unsigned short g_wrh[WTOT];
__device__ __align__(16) unsigned short g_wrl[WTOT];
__device__ int   g_deg[NN];
__device__ int   g_rowptr[NN + 1];
__device__ int   g_fill[NN];
__device__ int   g_csr[EE];
__device__ float g_pool[GG * 256];
__device__ int   g_gs[GG];
__device__ int   g_ge[GG];

// ---------------- helpers ----------------------------------------------------
__device__ __forceinline__ uint32_t smem_u32(const void* p) {
    uint32_t a;
    asm("{ .reg .u64 t; cvta.to.shared.u64 t, %1; cvt.u32.u64 %0, t; }" : "=r"(a) : "l"(p));
    return a;
}
// pack two f32 -> bf16x2 (low16 = a, high16 = b), round-to-nearest
__device__ __forceinline__ uint32_t pk2(float a, float b) {
    uint32_t r;
    asm("cvt.rn.bf16x2.f32 %0, %1, %2;" : "=r"(r) : "f"(b), "f"(a));
    return r;
}
// split pair of f32 into (hi bf16x2, lo bf16x2)
__device__ __forceinline__ void split2(float v0, float v1, uint32_t& hp, uint32_t& lp) {
    hp = pk2(v0, v1);
    float h0 = __uint_as_float(hp << 16);
    float h1 = __uint_as_float(hp & 0xFFFF0000u);
    lp = pk2(v0 - h0, v1 - h1);
}
__device__ __forceinline__ void ldm4(uint32_t* r, uint32_t a) {
    asm volatile("ldmatrix.sync.aligned.m8n8.x4.shared.b16 {%0,%1,%2,%3}, [%4];"
                 : "=r"(r[0]), "=r"(r[1]), "=r"(r[2]), "=r"(r[3]) : "r"(a));
}
__device__ __forceinline__ void ldm2(uint32_t* r, uint32_t a) {
    asm volatile("ldmatrix.sync.aligned.m8n8.x2.shared.b16 {%0,%1}, [%2];"
                 : "=r"(r[0]), "=r"(r[1]) : "r"(a));
}
#define MMA_BF16(c, a, b)                                                          \
    asm volatile("mma.sync.aligned.m16n8k16.row.col.f32.bf16.bf16.f32 "            \
        "{%0,%1,%2,%3}, {%4,%5,%6,%7}, {%8,%9}, {%0,%1,%2,%3};"                     \
        : "+f"((c)[0]), "+f"((c)[1]), "+f"((c)[2]), "+f"((c)[3])                    \
        : "r"((a)[0]), "r"((a)[1]), "r"((a)[2]), "r"((a)[3]),                       \
          "r"((b)[0]), "r"((b)[1]))
#define CP16(dst, src, sz)                                                         \
    asm volatile("cp.async.cg.shared.global [%0], [%1], 16, %2;"                    \
        :: "r"(dst), "l"(src), "r"(sz) : "memory")
#define CP_COMMIT() asm volatile("cp.async.commit_group;" ::: "memory")
#define CP_WAIT1()  asm volatile("cp.async.wait_group 1;" ::: "memory")
#define CP_WAIT0()  asm volatile("cp.async.wait_group 0;" ::: "memory")

// ---------------- CSR build -------------------------------------------------
__global__ void k_init() {
    int i = blockIdx.x * blockDim.x + threadIdx.x;
    if (i < NN) g_deg[i] = 0;
    if (i < GG) { g_gs[i] = NN; g_ge[i] = 0; }
}
__global__ void k_count(const int* __restrict__ ei) {
    int e = blockIdx.x * blockDim.x + threadIdx.x;
    if (e < EE) atomicAdd(&g_deg[ei[EE + e]], 1);
}
__global__ void k_scan() {
    __shared__ int part[1024];
    int tid = threadIdx.x;
    const int CH = (NN + 1023) / 1024;
    int base = tid * CH, s = 0;
    for (int i = 0; i < CH; i++) { int idx = base + i; if (idx < NN) s += g_deg[idx]; }
    part[tid] = s;
    __syncthreads();
    for (int off = 1; off < 1024; off <<= 1) {
        int v = (tid >= off) ? part[tid - off] : 0;
        __syncthreads(); part[tid] += v; __syncthreads();
    }
    int run = (tid == 0) ? 0 : part[tid - 1];
    for (int i = 0; i < CH; i++) {
        int idx = base + i;
        if (idx < NN) { int c = g_deg[idx]; g_rowptr[idx] = run; g_fill[idx] = run; run += c; }
    }
    if (tid == 1023) g_rowptr[NN] = part[1023];
}
__global__ void k_fillcsr(const int* __restrict__ ei) {
    int e = blockIdx.x * blockDim.x + threadIdx.x;
    if (e < EE) { int d = ei[EE + e]; int p = atomicAdd(&g_fill[d], 1); g_csr[p] = ei[e]; }
}

// ---------------- input split: x f32 -> hi/lo planes ------------------------
__global__ void k_cvtx(const float* __restrict__ x) {
    int i = blockIdx.x * 256 + threadIdx.x;
    if (i * 2 < NN * 128) {
        float v0 = x[i * 2], v1 = x[i * 2 + 1];
        uint32_t hp, lp;
        split2(v0, v1, hp, lp);
        ((uint32_t*)g_xh)[i] = hp;
        ((uint32_t*)g_xl)[i] = lp;
    }
}

// ---------------- weight transpose + split: W[k][n] -> hi/lo[n*K+k] ---------
__global__ void k_trp(const float* __restrict__ W, unsigned short* __restrict__ wh,
                      unsigned short* __restrict__ wl, int K, int Ncol) {
    int i = blockIdx.x * 256 + threadIdx.x;
    if (i < K * Ncol) {
        int k = i / Ncol, n = i % Ncol;
        float v = W[i];
        uint32_t hp = pk2(v, v);
        float hf = __uint_as_float(hp << 16);
        uint32_t lp = pk2(v - hf, 0.f);
        wh[(size_t)n * K + k] = (unsigned short)(hp & 0xFFFFu);
        wl[(size_t)n * K + k] = (unsigned short)(lp & 0xFFFFu);
    }
}

// ---------------- mean aggregation on planes (warp/node) --------------------
__global__ void k_agg(const unsigned short* __restrict__ ph, const unsigned short* __restrict__ pl,
                      unsigned short* __restrict__ oh, unsigned short* __restrict__ ol, int K) {
    int node = blockIdx.x * 8 + (threadIdx.x >> 5);
    if (node >= NN) return;
    int lane = threadIdx.x & 31;
    int beg = g_rowptr[node], end = g_rowptr[node + 1];
    int npp = K >> 7;  // 1,2,2,4 passes of 4 elems/lane
    float acc[4][4];
#pragma unroll
    for (int p = 0; p < 4; p++)
#pragma unroll
        for (int j = 0; j < 4; j++) acc[p][j] = 0.f;
    for (int e = beg; e < end; e++) {
        int s = g_csr[e];
        const uint2* rh = (const uint2*)(ph + (size_t)s * K);
        const uint2* rl = (const uint2*)(pl + (size_t)s * K);
        for (int p = 0; p < npp; p++) {
            uint2 h2 = rh[lane + (p << 5)];
            uint2 l2 = rl[lane + (p << 5)];
            acc[p][0] += __uint_as_float(h2.x << 16) + __uint_as_float(l2.x << 16);
            acc[p][1] += __uint_as_float(h2.x & 0xFFFF0000u) + __uint_as_float(l2.x & 0xFFFF0000u);
            acc[p][2] += __uint_as_float(h2.y << 16) + __uint_as_float(l2.y << 16);
            acc[p][3] += __uint_as_float(h2.y & 0xFFFF0000u) + __uint_as_float(l2.y & 0xFFFF0000u);
        }
    }
    int d = end - beg;
    float inv = 1.0f / (float)(d > 0 ? d : 1);
    uint2* wh = (uint2*)(oh + (size_t)node * K);
    uint2* wl = (uint2*)(ol + (size_t)node * K);
    for (int p = 0; p < npp; p++) {
        float v0 = acc[p][0] * inv, v1 = acc[p][1] * inv;
        float v2 = acc[p][2] * inv, v3 = acc[p][3] * inv;
        uint32_t hp0, lp0, hp1, lp1;
        split2(v0, v1, hp0, lp0);
        split2(v2, v3, hp1, lp1);
        wh[lane + (p << 5)] = make_uint2(hp0, hp1);
        wl[lane + (p << 5)] = make_uint2(lp0, lp1);
    }
}

// ---------------- bf16 3x-split dual GEMM, cp.async double-buffered ---------
// Tiles per stage: Ahi/Alo/Bhi/Blo, each 128 rows x 32 bf16 (64B rows, SW64).
#define T_AH 0
#define T_AL 8192
#define T_BH 16384
#define T_BL 24576
#define STAGE_B 32768
#define SMEM_BYTES 65536

template <bool LEAKY>
__global__ void __launch_bounds__(256) k_gemm_tc(
    const unsigned short* __restrict__ a1h, const unsigned short* __restrict__ a1l,
    const unsigned short* __restrict__ a2h, const unsigned short* __restrict__ a2l,
    const unsigned short* __restrict__ b1h, const unsigned short* __restrict__ b1l,
    const unsigned short* __restrict__ b2h, const unsigned short* __restrict__ b2l,
    const float* __restrict__ bias,
    unsigned short* __restrict__ Oh, unsigned short* __restrict__ Ol,
    int K, int DOUT)
{
    extern __shared__ char smem[];
    const uint32_t sb = smem_u32(smem);
    const int t = threadIdx.x, lane = t & 31, wid = t >> 5;
    const int wr = wid >> 2, wc = wid & 3;
    const int m0 = blockIdx.y * 128, n0 = blockIdx.x * 128;
    const int nc = K / 32, tot = 2 * nc;

    float acc[4][4][4];
#pragma unroll
    for (int i = 0; i < 4; i++)
#pragma unroll
        for (int j = 0; j < 4; j++)
#pragma unroll
            for (int k = 0; k < 4; k++) acc[i][j][k] = 0.f;

    // fill constants: thread handles granule g of rows row0 and row0+64 per tile
    const int row0 = t >> 2;
    const int g = t & 3;
    const uint32_t d0 = (uint32_t)row0 * 64 + (((uint32_t)g * 16) ^ (((uint32_t)row0 & 6) << 3));
    const uint32_t d1 = d0 + 4096;  // row0+64: same swizzle bits
    const int gr0 = m0 + row0, gr1 = m0 + row0 + 64;
    const uint32_t sz0 = (gr0 < NN) ? 16u : 0u;
    const uint32_t sz1 = (gr1 < NN) ? 16u : 0u;
    const size_t aoff0 = (size_t)(gr0 < NN ? gr0 : NN - 1) * K + g * 8;
    const size_t aoff1 = (size_t)(gr1 < NN ? gr1 : NN - 1) * K + g * 8;
    const size_t boff0 = (size_t)(n0 + row0) * K + g * 8;
    const size_t boff1 = (size_t)(n0 + row0 + 64) * K + g * 8;

    // MMA fragment address constants
    const uint32_t fxor = ((uint32_t)(lane & 6)) << 3;
    const int ra = wr * 64 + (lane & 7) + ((lane >> 3) & 1) * 8;
    const uint32_t achk = ((uint32_t)(lane >> 4)) * 16;
    const int rb = wc * 32 + (lane & 7);
    const uint32_t bchk = ((uint32_t)((lane >> 3) & 1)) * 16;

#define FILL(ch, stg) do {                                                         \
    const unsigned short *ah_, *al_, *bh_, *bl_; int kb_;                          \
    if ((ch) < nc) { ah_ = a1h; al_ = a1l; bh_ = b1h; bl_ = b1l; kb_ = (ch) * 32; } \
    else           { ah_ = a2h; al_ = a2l; bh_ = b2h; bl_ = b2l; kb_ = ((ch) - nc) * 32; } \
    uint32_t s0_ = sb + (stg) * STAGE_B;                                           \
    CP16(s0_ + T_AH + d0, ah_ + aoff0 + kb_, sz0);                                 \
    CP16(s0_ + T_AH + d1, ah_ + aoff1 + kb_, sz1);                                 \
    CP16(s0_ + T_AL + d0, al_ + aoff0 + kb_, sz0);                                 \
    CP16(s0_ + T_AL + d1, al_ + aoff1 + kb_, sz1);                                 \
    CP16(s0_ + T_BH + d0, bh_ + boff0 + kb_, 16u);                                 \
    CP16(s0_ + T_BH + d1, bh_ + boff1 + kb_, 16u);                                 \
    CP16(s0_ + T_BL + d0, bl_ + boff0 + kb_, 16u);                                 \
    CP16(s0_ + T_BL + d1, bl_ + boff1 + kb_, 16u);                                 \
    CP_COMMIT();                                                                   \
} while (0)

    FILL(0, 0);

    for (int ch = 0; ch < tot; ch++) {
        __syncthreads();  // prior MMA reads done before overwriting other stage
        if (ch + 1 < tot) { FILL(ch + 1, (ch + 1) & 1); CP_WAIT1(); }
        else              { CP_WAIT0(); }
        __syncthreads();

        const uint32_t s0 = sb + (ch & 1) * STAGE_B;
#pragma unroll
        for (int ks = 0; ks < 2; ks++) {
            const uint32_t cA = ((uint32_t)(ks * 32) + achk) ^ fxor;
            const uint32_t cB = ((uint32_t)(ks * 32) + bchk) ^ fxor;
            uint32_t ah[4][4], al[4][4], bh[4][2], bl[4][2];
#pragma unroll
            for (int mt = 0; mt < 4; mt++) {
                uint32_t rbase = (uint32_t)(ra + mt * 16) * 64;
                ldm4(ah[mt], s0 + T_AH + rbase + cA);
                ldm4(al[mt], s0 + T_AL + rbase + cA);
            }
#pragma unroll
            for (int nt = 0; nt < 4; nt++) {
                uint32_t rbase = (uint32_t)(rb + nt * 8) * 64;
                ldm2(bh[nt], s0 + T_BH + rbase + cB);
                ldm2(bl[nt], s0 + T_BL + rbase + cB);
            }
#pragma unroll
            for (int mt = 0; mt < 4; mt++)
#pragma unroll
                for (int nt = 0; nt < 4; nt++) {
                    MMA_BF16(acc[mt][nt], ah[mt], bh[nt]);
                    MMA_BF16(acc[mt][nt], ah[mt], bl[nt]);
                    MMA_BF16(acc[mt][nt], al[mt], bh[nt]);
                }
        }
    }
#undef FILL

    // epilogue: bias + optional leaky; write hi/lo planes
#pragma unroll
    for (int mt = 0; mt < 4; mt++) {
        int r0 = m0 + wr * 64 + mt * 16 + (lane >> 2);
        int r1 = r0 + 8;
#pragma unroll
        for (int nt = 0; nt < 4; nt++) {
            int c0 = n0 + wc * 32 + nt * 8 + (lane & 3) * 2;
            float2 b2 = *(const float2*)(bias + c0);
            float v0 = acc[mt][nt][0] + b2.x;
            float v1 = acc[mt][nt][1] + b2.y;
            float v2 = acc[mt][nt][2] + b2.x;
            float v3 = acc[mt][nt][3] + b2.y;
            if (LEAKY) {
                v0 = v0 >= 0.f ? v0 : 0.01f * v0;
                v1 = v1 >= 0.f ? v1 : 0.01f * v1;
                v2 = v2 >= 0.f ? v2 : 0.01f * v2;
                v3 = v3 >= 0.f ? v3 : 0.01f * v3;
            }
            uint32_t hp, lp;
            if (r0 < NN) {
                split2(v0, v1, hp, lp);
                *(uint32_t*)(Oh + (size_t)r0 * DOUT + c0) = hp;
                *(uint32_t*)(Ol + (size_t)r0 * DOUT + c0) = lp;
            }
            if (r1 < NN) {
                split2(v2, v3, hp, lp);
                *(uint32_t*)(Oh + (size_t)r1 * DOUT + c0) = hp;
                *(uint32_t*)(Ol + (size_t)r1 * DOUT + c0) = lp;
            }
        }
    }
}

// ---------------- pool + head ------------------------------------------------
__global__ void k_bounds(const int* __restrict__ batch) {
    int n = blockIdx.x * blockDim.x + threadIdx.x;
    if (n < NN) {
        int b = batch[n];
        atomicMin(&g_gs[b], n);
        atomicMax(&g_ge[b], n + 1);
    }
}
__global__ void k_pool(const unsigned short* __restrict__ Hh,
                       const unsigned short* __restrict__ Hl) {
    int g = blockIdx.x, f = threadIdx.x;
    int s = g_gs[g], e = g_ge[g];
    float sum = 0.f;
    for (int n = s; n < e; n++) {
        size_t idx = (size_t)n * 256 + f;
        sum += __uint_as_float(((uint32_t)Hh[idx]) << 16)
             + __uint_as_float(((uint32_t)Hl[idx]) << 16);
    }
    int c = e - s; if (c < 1) c = 1;
    g_pool[g * 256 + f] = sum / (float)c;
}
__global__ void k_final(const float* __restrict__ Wlin, const float* __restrict__ blin,
                        float* __restrict__ out) {
    int idx = threadIdx.x;
    if (idx >= GG * 6) return;
    int g = idx / 6, o = idx % 6;
    float s = blin[o];
#pragma unroll 8
    for (int k = 0; k < 256; k++) s += g_pool[g * 256 + k] * Wlin[k * 6 + o];
    out[idx] = s;
}

// ---------------- launcher ----------------------------------------------------
extern "C" void kernel_launch(void* const* d_in, const int* in_sizes, int n_in,
                              void* d_out, int out_size) {
    const float* x     = (const float*)d_in[0];
    const int*   ei    = (const int*)d_in[1];
    const int*   batch = (const int*)d_in[2];
    const float* Wl[6]; const float* blp[6]; const float* Wr[6];
    for (int l = 0; l < 6; l++) {
        Wl[l]  = (const float*)d_in[3 + 3 * l];
        blp[l] = (const float*)d_in[4 + 3 * l];
        Wr[l]  = (const float*)d_in[5 + 3 * l];
    }
    const float* Wlin = (const float*)d_in[21];
    const float* blin = (const float*)d_in[22];
    float* out = (float*)d_out;

    unsigned short *xh, *xl, *agh, *agl, *Ah, *Al, *Bh, *Bl, *wlh, *wll, *wrh, *wrl;
    cudaGetSymbolAddress((void**)&xh, g_xh);   cudaGetSymbolAddress((void**)&xl, g_xl);
    cudaGetSymbolAddress((void**)&agh, g_agh); cudaGetSymbolAddress((void**)&agl, g_agl);
    cudaGetSymbolAddress((void**)&Ah, g_Ah);   cudaGetSymbolAddress((void**)&Al, g_Al);
    cudaGetSymbolAddress((void**)&Bh, g_Bh);   cudaGetSymbolAddress((void**)&Bl, g_Bl);
    cudaGetSymbolAddress((void**)&wlh, g_wlh); cudaGetSymbolAddress((void**)&wll, g_wll);
    cudaGetSymbolAddress((void**)&wrh, g_wrh); cudaGetSymbolAddress((void**)&wrl, g_wrl);

    cudaFuncSetAttribute(k_gemm_tc<true>,  cudaFuncAttributeMaxDynamicSharedMemorySize, SMEM_BYTES);
    cudaFuncSetAttribute(k_gemm_tc<false>, cudaFuncAttributeMaxDynamicSharedMemorySize, SMEM_BYTES);

    const int din[6]  = {128, 256, 256, 512, 512, 256};
    const int dout[6] = {256, 256, 512, 512, 256, 256};
    const int woff[6] = {0, 32768, 98304, 229376, 491520, 622592};

    // CSR build
    k_init<<<(NN + 255) / 256, 256>>>();
    k_count<<<(EE + 255) / 256, 256>>>(ei);
    k_scan<<<1, 1024>>>();
    k_fillcsr<<<(EE + 255) / 256, 256>>>(ei);

    // input split + weight transpose/split
    k_cvtx<<<(NN * 128 / 2 + 255) / 256, 256>>>(x);
    for (int l = 0; l < 6; l++) {
        int sz = din[l] * dout[l];
        k_trp<<<(sz + 255) / 256, 256>>>(Wl[l], wlh + woff[l], wll + woff[l], din[l], dout[l]);
        k_trp<<<(sz + 255) / 256, 256>>>(Wr[l], wrh + woff[l], wrl + woff[l], din[l], dout[l]);
    }

    const unsigned short* inh = xh; const unsigned short* inl = xl;
    for (int l = 0; l < 6; l++) {
        unsigned short* oh = (l & 1) ? Bh : Ah;
        unsigned short* ol = (l & 1) ? Bl : Al;
        k_agg<<<(NN + 7) / 8, 256>>>(inh, inl, agh, agl, din[l]);
        dim3 grid(dout[l] / 128, (NN + 127) / 128);
        if (l < 5)
            k_gemm_tc<true><<<grid, 256, SMEM_BYTES>>>(agh, agl, inh, inl,
                wlh + woff[l], wll + woff[l], wrh + woff[l], wrl + woff[l],
                blp[l], oh, ol, din[l], dout[l]);
        else
            k_gemm_tc<false><<<grid, 256, SMEM_BYTES>>>(agh, agl, inh, inl,
                wlh + woff[l], wll + woff[l], wrh + woff[l], wrl + woff[l],
                blp[l], oh, ol, din[l], dout[l]);
        inh = oh; inl = ol;
    }
    k_bounds<<<(NN + 255) / 256, 256>>>(batch);
    k_pool<<<GG, 256>>>(inh, inl);
    k_final<<<1, 384>>>(Wlin, blin, out);
}